// round 2
// baseline (speedup 1.0000x reference)
#include <cuda_runtime.h>

#define B_  4
#define T_  2048
#define C_  1024
#define H_  128
#define BT_ (B_ * T_)

// Scratch for Q, K, V projections (static device arrays: allocation-free).
__device__ float g_Q[BT_ * H_];
__device__ float g_K[BT_ * H_];
__device__ float g_V[BT_ * H_];

// ---------------------------------------------------------------------------
// Kernel 1: QKV projection.  out = x @ W, for W in {Wq, Wk, Wv} (blockIdx.y).
// Tiling: BM=64 rows, BN=128 cols (full H), BK=16. 256 threads, 4x8 microtile.
// ---------------------------------------------------------------------------
__global__ __launch_bounds__(256, 1) void proj_kernel(
    const float* __restrict__ x,
    const float* __restrict__ Wq,
    const float* __restrict__ Wk,
    const float* __restrict__ Wv)
{
    __shared__ float As[16][68];    // [k][row], padded
    __shared__ float Bs[16][132];   // [k][col], padded

    const int w = blockIdx.y;
    const float* __restrict__ W = (w == 0) ? Wq : (w == 1) ? Wk : Wv;
    float* out = (w == 0) ? g_Q : (w == 1) ? g_K : g_V;

    const int m0  = blockIdx.x * 64;
    const int tid = threadIdx.x;
    const int tr  = tid >> 4;        // 0..15 -> rows tr*4..tr*4+3
    const int tc  = tid & 15;        // 0..15 -> cols tc*8..tc*8+7

    const int arow = tid >> 2;           // 0..63
    const int acol = (tid & 3) << 2;     // 0,4,8,12
    const int brow = tid >> 4;           // 0..15
    const int bcol = (tid & 15) << 3;    // 0..120

    float acc[4][8];
#pragma unroll
    for (int i = 0; i < 4; i++)
#pragma unroll
        for (int j = 0; j < 8; j++) acc[i][j] = 0.f;

    for (int k0 = 0; k0 < C_; k0 += 16) {
        float4 av  = *(const float4*)&x[(m0 + arow) * C_ + k0 + acol];
        float4 bv0 = *(const float4*)&W[(k0 + brow) * H_ + bcol];
        float4 bv1 = *(const float4*)&W[(k0 + brow) * H_ + bcol + 4];
        As[acol + 0][arow] = av.x;
        As[acol + 1][arow] = av.y;
        As[acol + 2][arow] = av.z;
        As[acol + 3][arow] = av.w;
        *(float4*)&Bs[brow][bcol]     = bv0;
        *(float4*)&Bs[brow][bcol + 4] = bv1;
        __syncthreads();

#pragma unroll
        for (int kk = 0; kk < 16; kk++) {
            float4 a  = *(const float4*)&As[kk][tr * 4];
            float4 b0 = *(const float4*)&Bs[kk][tc * 8];
            float4 b1 = *(const float4*)&Bs[kk][tc * 8 + 4];
            float ar[4] = {a.x, a.y, a.z, a.w};
            float br[8] = {b0.x, b0.y, b0.z, b0.w, b1.x, b1.y, b1.z, b1.w};
#pragma unroll
            for (int i = 0; i < 4; i++)
#pragma unroll
                for (int j = 0; j < 8; j++)
                    acc[i][j] += ar[i] * br[j];
        }
        __syncthreads();
    }

#pragma unroll
    for (int i = 0; i < 4; i++) {
        int row = m0 + tr * 4 + i;
        float4 v0 = make_float4(acc[i][0], acc[i][1], acc[i][2], acc[i][3]);
        float4 v1 = make_float4(acc[i][4], acc[i][5], acc[i][6], acc[i][7]);
        *(float4*)&out[row * H_ + tc * 8]     = v0;
        *(float4*)&out[row * H_ + tc * 8 + 4] = v1;
    }
}

// ---------------------------------------------------------------------------
// Kernel 2: flash attention, fp32, causal.
// One CTA = 64 query rows of one batch. Loops over 64-key tiles up to diag.
// 256 threads: S-tile mapping (ty,tx) -> 4x4 of S[64][64];
//              O-tile mapping (ty,tx) -> 4 rows x 8 cols of O[64][128].
// Same thread owns the same 4 query rows in both mappings -> m/l/corr local.
// ---------------------------------------------------------------------------
#define QS(r, c) smQ[(r) * 132 + (c)]
#define KS(r, c) smK[(r) * 132 + (c)]
#define VS(r, c) smV[(r) * 132 + (c)]
#define PS(r, c) smP[(r) * 68 + (c)]

__global__ __launch_bounds__(256, 1) void attn_kernel(float* __restrict__ out)
{
    extern __shared__ float sm[];
    float* smQ = sm;
    float* smK = smQ + 64 * 132;
    float* smV = smK + 64 * 132;
    float* smP = smV + 64 * 132;

    const int b  = blockIdx.y;
    const int m0 = blockIdx.x * 64;
    const float* __restrict__ Qg = g_Q + b * T_ * H_;
    const float* __restrict__ Kg = g_K + b * T_ * H_;
    const float* __restrict__ Vg = g_V + b * T_ * H_;

    const int tid = threadIdx.x;
    const int ty  = tid >> 4;       // 0..15
    const int tx  = tid & 15;       // 0..15
    const int r0  = ty * 4;         // local query rows r0..r0+3
    const int c0s = tx * 4;         // S cols
    const int c0o = tx * 8;         // O cols

    // Load Q tile (64 x 128)
#pragma unroll
    for (int i = 0; i < 8; i++) {
        int f = i * 256 + tid;
        int row = f >> 5, c = (f & 31) << 2;
        *(float4*)&QS(row, c) = *(const float4*)&Qg[(m0 + row) * H_ + c];
    }

    float m_run[4], l_run[4], o[4][8];
#pragma unroll
    for (int i = 0; i < 4; i++) { m_run[i] = -1e30f; l_run[i] = 0.f; }
#pragma unroll
    for (int i = 0; i < 4; i++)
#pragma unroll
        for (int j = 0; j < 8; j++) o[i][j] = 0.f;

    const int nk = (m0 >> 6) + 1;             // key tiles (causal)
    const float inv_scale = 0.03125f;         // C^-0.5 = 1/32

    for (int t = 0; t < nk; t++) {
        const int s0 = t * 64;
        __syncthreads();   // protect K/V/P from previous iteration's readers
#pragma unroll
        for (int i = 0; i < 8; i++) {
            int f = i * 256 + tid;
            int row = f >> 5, c = (f & 31) << 2;
            *(float4*)&KS(row, c) = *(const float4*)&Kg[(s0 + row) * H_ + c];
            *(float4*)&VS(row, c) = *(const float4*)&Vg[(s0 + row) * H_ + c];
        }
        __syncthreads();

        // S = Q @ K^T  (4x4 per thread), vectorized over k
        float s[4][4];
#pragma unroll
        for (int i = 0; i < 4; i++)
#pragma unroll
            for (int j = 0; j < 4; j++) s[i][j] = 0.f;

        for (int k = 0; k < H_; k += 4) {
            float4 q[4], kv[4];
#pragma unroll
            for (int i = 0; i < 4; i++) q[i]  = *(const float4*)&QS(r0 + i, k);
#pragma unroll
            for (int j = 0; j < 4; j++) kv[j] = *(const float4*)&KS(c0s + j, k);
#pragma unroll
            for (int i = 0; i < 4; i++)
#pragma unroll
                for (int j = 0; j < 4; j++) {
                    s[i][j] += q[i].x * kv[j].x;
                    s[i][j] += q[i].y * kv[j].y;
                    s[i][j] += q[i].z * kv[j].z;
                    s[i][j] += q[i].w * kv[j].w;
                }
        }

#pragma unroll
        for (int i = 0; i < 4; i++)
#pragma unroll
            for (int j = 0; j < 4; j++) s[i][j] *= inv_scale;

        if (t == nk - 1) {  // diagonal tile: causal mask (key > query)
#pragma unroll
            for (int i = 0; i < 4; i++)
#pragma unroll
                for (int j = 0; j < 4; j++)
                    if (c0s + j > r0 + i) s[i][j] = -1e30f;
        }

        // Online softmax update (row stats across 16-thread half-warp groups)
#pragma unroll
        for (int i = 0; i < 4; i++) {
            float mx = fmaxf(fmaxf(s[i][0], s[i][1]), fmaxf(s[i][2], s[i][3]));
            mx = fmaxf(mx, __shfl_xor_sync(0xffffffffu, mx, 8));
            mx = fmaxf(mx, __shfl_xor_sync(0xffffffffu, mx, 4));
            mx = fmaxf(mx, __shfl_xor_sync(0xffffffffu, mx, 2));
            mx = fmaxf(mx, __shfl_xor_sync(0xffffffffu, mx, 1));
            float mnew = fmaxf(m_run[i], mx);
            float corr = __expf(m_run[i] - mnew);
            m_run[i] = mnew;
            float ps = 0.f;
#pragma unroll
            for (int j = 0; j < 4; j++) {
                float p = __expf(s[i][j] - mnew);
                ps += p;
                PS(r0 + i, c0s + j) = p;
            }
            ps += __shfl_xor_sync(0xffffffffu, ps, 8);
            ps += __shfl_xor_sync(0xffffffffu, ps, 4);
            ps += __shfl_xor_sync(0xffffffffu, ps, 2);
            ps += __shfl_xor_sync(0xffffffffu, ps, 1);
            l_run[i] = l_run[i] * corr + ps;
#pragma unroll
            for (int j = 0; j < 8; j++) o[i][j] *= corr;
        }
        __syncthreads();

        // O += P @ V  (4 rows x 8 cols per thread), vectorized over s
        for (int s4 = 0; s4 < 64; s4 += 4) {
            float p[4][4];
#pragma unroll
            for (int i = 0; i < 4; i++) {
                float4 pv = *(const float4*)&PS(r0 + i, s4);
                p[i][0] = pv.x; p[i][1] = pv.y; p[i][2] = pv.z; p[i][3] = pv.w;
            }
#pragma unroll
            for (int ss = 0; ss < 4; ss++) {
                float4 v0 = *(const float4*)&VS(s4 + ss, c0o);
                float4 v1 = *(const float4*)&VS(s4 + ss, c0o + 4);
#pragma unroll
                for (int i = 0; i < 4; i++) {
                    float pi = p[i][ss];
                    o[i][0] += pi * v0.x; o[i][1] += pi * v0.y;
                    o[i][2] += pi * v0.z; o[i][3] += pi * v0.w;
                    o[i][4] += pi * v1.x; o[i][5] += pi * v1.y;
                    o[i][6] += pi * v1.z; o[i][7] += pi * v1.w;
                }
            }
        }
    }

    // Final normalize + store
#pragma unroll
    for (int i = 0; i < 4; i++) {
        float inv_l = 1.f / l_run[i];
        int row = m0 + r0 + i;
        float4 v0 = make_float4(o[i][0] * inv_l, o[i][1] * inv_l,
                                o[i][2] * inv_l, o[i][3] * inv_l);
        float4 v1 = make_float4(o[i][4] * inv_l, o[i][5] * inv_l,
                                o[i][6] * inv_l, o[i][7] * inv_l);
        *(float4*)&out[(b * T_ + row) * H_ + c0o]     = v0;
        *(float4*)&out[(b * T_ + row) * H_ + c0o + 4] = v1;
    }
}

// ---------------------------------------------------------------------------
// Launch
// ---------------------------------------------------------------------------
extern "C" void kernel_launch(void* const* d_in, const int* in_sizes, int n_in,
                              void* d_out, int out_size)
{
    const float* x  = (const float*)d_in[0];
    const float* Wq = (const float*)d_in[1];
    const float* Wk = (const float*)d_in[2];
    const float* Wv = (const float*)d_in[3];
    // d_in[4] = mask: tril by construction -> causal logic used directly.
    float* out = (float*)d_out;

    dim3 gp(BT_ / 64, 3);
    proj_kernel<<<gp, 256>>>(x, Wq, Wk, Wv);

    const size_t smem = (size_t)(64 * 132 * 3 + 64 * 68) * sizeof(float); // 118784 B
    cudaFuncSetAttribute((const void*)attn_kernel,
                         cudaFuncAttributeMaxDynamicSharedMemorySize, (int)smem);
    dim3 ga(T_ / 64, B_);
    attn_kernel<<<ga, 256, smem>>>(out);
}

// round 4
// speedup vs baseline: 5.3559x; 5.3559x over previous
#include <cuda_runtime.h>
#include <cstdint>

#define B_  4
#define T_  2048
#define C_  1024
#define H_  128
#define BT_ (B_ * T_)
#define NUNITS 320   // split-K attention work units: 4 batches * 80

// Static device scratch (allocation-free).
__device__ float g_Q[BT_ * H_];
__device__ float g_K[BT_ * H_];
__device__ float g_V[BT_ * H_];
__device__ float g_Opart[NUNITS * 64 * H_];  // unnormalized partial O
__device__ float g_ml[NUNITS * 64 * 2];      // per-row (m, l)

// ---------------------------------------------------------------------------
// TF32 warp MMA helpers (baseline PTX, works on compute_103 target)
// ---------------------------------------------------------------------------
__device__ __forceinline__ float to_tf32(float x) {
    float r;
    asm("cvt.rna.tf32.f32 %0, %1;" : "=f"(r) : "f"(x));
    return r;
}

// D(16x8) += A(16x8,row) * B(8x8,col).  a: 4 regs, b: 2 regs, d: 4 f32.
__device__ __forceinline__ void mma_tf32(float* d, const uint32_t* a,
                                         uint32_t b0, uint32_t b1) {
    asm volatile(
        "mma.sync.aligned.m16n8k8.row.col.f32.tf32.tf32.f32 "
        "{%0,%1,%2,%3}, {%4,%5,%6,%7}, {%8,%9}, {%0,%1,%2,%3};"
        : "+f"(d[0]), "+f"(d[1]), "+f"(d[2]), "+f"(d[3])
        : "r"(a[0]), "r"(a[1]), "r"(a[2]), "r"(a[3]), "r"(b0), "r"(b1));
}

// ---------------------------------------------------------------------------
// Kernel 1: QKV projection via TF32 mma.sync.
// CTA: 128(M) x 128(N), 256 thr = 8 warps in 4(M) x 2(N); warp = 32x64.
// W is [C,H] = B[k][n] which is exactly mma's .col B layout -> no transpose.
// ---------------------------------------------------------------------------
#define AS(r, c) sA[(r) * 36 + (c)]
#define BS(r, c) sB[(r) * 136 + (c)]

__global__ __launch_bounds__(256, 2) void proj_mma(
    const float* __restrict__ x,
    const float* __restrict__ Wq,
    const float* __restrict__ Wk,
    const float* __restrict__ Wv)
{
    __shared__ float sA[128 * 36];   // x slab [128][32], pad 36
    __shared__ float sB[32 * 136];   // W slab [32][128], pad 136

    const int w = blockIdx.y;
    const float* __restrict__ W = (w == 0) ? Wq : (w == 1) ? Wk : Wv;
    float* outp = (w == 0) ? g_Q : (w == 1) ? g_K : g_V;

    const int m0   = blockIdx.x * 128;
    const int tid  = threadIdx.x;
    const int wid  = tid >> 5, lane = tid & 31;
    const int g    = lane >> 2, tig = lane & 3;
    const int wm   = (wid & 3) * 32;      // warp M offset
    const int wn   = (wid >> 2) * 64;     // warp N offset

    float acc[2][8][4];
#pragma unroll
    for (int mt = 0; mt < 2; mt++)
#pragma unroll
        for (int nt = 0; nt < 8; nt++)
#pragma unroll
            for (int i = 0; i < 4; i++) acc[mt][nt][i] = 0.f;

    for (int k0 = 0; k0 < C_; k0 += 32) {
        __syncthreads();
        // Load A slab (128x32) and B slab (32x128), tf32-rounded.
#pragma unroll
        for (int i = 0; i < 4; i++) {
            int idx = i * 256 + tid;
            int ra = idx >> 3, ca = (idx & 7) * 4;
            float4 va = *(const float4*)&x[(m0 + ra) * C_ + k0 + ca];
            AS(ra, ca + 0) = to_tf32(va.x);
            AS(ra, ca + 1) = to_tf32(va.y);
            AS(ra, ca + 2) = to_tf32(va.z);
            AS(ra, ca + 3) = to_tf32(va.w);
            int rb = idx >> 5, cb = (idx & 31) * 4;
            float4 vb = *(const float4*)&W[(k0 + rb) * H_ + cb];
            BS(rb, cb + 0) = to_tf32(vb.x);
            BS(rb, cb + 1) = to_tf32(vb.y);
            BS(rb, cb + 2) = to_tf32(vb.z);
            BS(rb, cb + 3) = to_tf32(vb.w);
        }
        __syncthreads();

#pragma unroll
        for (int kk = 0; kk < 32; kk += 8) {
            uint32_t a[2][4];
#pragma unroll
            for (int mt = 0; mt < 2; mt++) {
                int rm = wm + mt * 16;
                a[mt][0] = __float_as_uint(AS(rm + g,     kk + tig));
                a[mt][1] = __float_as_uint(AS(rm + g + 8, kk + tig));
                a[mt][2] = __float_as_uint(AS(rm + g,     kk + tig + 4));
                a[mt][3] = __float_as_uint(AS(rm + g + 8, kk + tig + 4));
            }
#pragma unroll
            for (int nt = 0; nt < 8; nt++) {
                uint32_t b0 = __float_as_uint(BS(kk + tig,     wn + nt * 8 + g));
                uint32_t b1 = __float_as_uint(BS(kk + tig + 4, wn + nt * 8 + g));
                mma_tf32(acc[0][nt], a[0], b0, b1);
                mma_tf32(acc[1][nt], a[1], b0, b1);
            }
        }
    }

    // Store: c0 -> (row g, col 2*tig), c1 -> +1 col, c2/c3 -> row g+8.
#pragma unroll
    for (int mt = 0; mt < 2; mt++)
#pragma unroll
        for (int nt = 0; nt < 8; nt++) {
            int rA = m0 + wm + mt * 16 + g;
            int cc = wn + nt * 8 + tig * 2;
            *(float2*)&outp[rA * H_ + cc]       = make_float2(acc[mt][nt][0], acc[mt][nt][1]);
            *(float2*)&outp[(rA + 8) * H_ + cc] = make_float2(acc[mt][nt][2], acc[mt][nt][3]);
        }
}

// ---------------------------------------------------------------------------
// Kernel 2: attention partial (split-K flash), TF32 mma for S and PV.
// Unit = (batch, qtile qt, chunk ch): key tiles [8ch, min(8ch+8, qt+1)).
// smem: Q(tf32) 64x132 | KV(tf32, shared K then V) 64x132 | P 64x68 | corr 64.
// S-phase warps: 4(M)x2(N), warp=16x32.  PV warps: 4(M)x2(N), warp=16x64.
// Softmax: round-2 proven mapping (ty,tx -> 4x4 block), corr via smCorr.
// ---------------------------------------------------------------------------
#define QS(r, c)  smQ[(r) * 132 + (c)]
#define KVS(r, c) smKV[(r) * 132 + (c)]
#define PS(r, c)  smP[(r) * 68 + (c)]
#define ATTN_SMEM ((size_t)(64 * 132 * 2 + 64 * 68 + 64) * sizeof(float))

__global__ __launch_bounds__(256, 2) void attn_part() {
    extern __shared__ float smf[];
    float* smQ    = smf;
    float* smKV   = smQ + 64 * 132;
    float* smP    = smKV + 64 * 132;
    float* smCorr = smP + 64 * 68;

    const int bx = blockIdx.x;
    const int b = bx / 80;
    const int u = bx % 80;
    int qt, ch;
    if (u < 8)       { qt = u;                  ch = 0; }
    else if (u < 24) { qt = 8 + ((u - 8) >> 1); ch = (u - 8) & 1; }
    else if (u < 48) { int v = u - 24; qt = 16 + v / 3; ch = v - 3 * (v / 3); }
    else             { int v = u - 48; qt = 24 + (v >> 2); ch = v & 3; }
    const int m0 = qt * 64;
    const int t0 = ch * 8;
    const int t1 = min(t0 + 8, qt + 1);

    const float* __restrict__ Qg = g_Q + b * T_ * H_;
    const float* __restrict__ Kg = g_K + b * T_ * H_;
    const float* __restrict__ Vg = g_V + b * T_ * H_;

    const int tid  = threadIdx.x;
    const int wid  = tid >> 5, lane = tid & 31;
    const int g    = lane >> 2, tig = lane & 3;
    const int wm   = (wid & 3) * 16;      // warp M offset (S and O)
    const int wns  = (wid >> 2) * 32;     // warp N offset, S phase
    const int wno  = (wid >> 2) * 64;     // warp N offset, PV phase
    const int ty   = tid >> 4, tx = tid & 15;
    const int r0   = ty * 4, c0s = tx * 4;

    // Load Q tile (64x128), tf32-rounded.
#pragma unroll
    for (int i = 0; i < 8; i++) {
        int f = i * 256 + tid;
        int row = f >> 5, c = (f & 31) << 2;
        float4 v = *(const float4*)&Qg[(m0 + row) * H_ + c];
        QS(row, c + 0) = to_tf32(v.x);
        QS(row, c + 1) = to_tf32(v.y);
        QS(row, c + 2) = to_tf32(v.z);
        QS(row, c + 3) = to_tf32(v.w);
    }

    float m_run[4], l_run[4];
#pragma unroll
    for (int i = 0; i < 4; i++) { m_run[i] = -1e30f; l_run[i] = 0.f; }
    float oacc[8][4];
#pragma unroll
    for (int nt = 0; nt < 8; nt++)
#pragma unroll
        for (int i = 0; i < 4; i++) oacc[nt][i] = 0.f;

    const float inv_scale = 0.03125f;  // C^-0.5

    for (int t = t0; t < t1; t++) {
        const int s0 = t * 64;
        __syncthreads();  // prev iteration's PV done with smP/smKV
        // Load K tile (64x128), tf32.
#pragma unroll
        for (int i = 0; i < 8; i++) {
            int f = i * 256 + tid;
            int row = f >> 5, c = (f & 31) << 2;
            float4 v = *(const float4*)&Kg[(s0 + row) * H_ + c];
            KVS(row, c + 0) = to_tf32(v.x);
            KVS(row, c + 1) = to_tf32(v.y);
            KVS(row, c + 2) = to_tf32(v.z);
            KVS(row, c + 3) = to_tf32(v.w);
        }
        __syncthreads();

        // S = Q @ K^T : warp computes 16x32, 4 n-tiles, K=128 in 16 steps.
        float sacc[4][4];
#pragma unroll
        for (int nt = 0; nt < 4; nt++)
#pragma unroll
            for (int i = 0; i < 4; i++) sacc[nt][i] = 0.f;

#pragma unroll 4
        for (int kk = 0; kk < 128; kk += 8) {
            uint32_t a[4];
            a[0] = __float_as_uint(QS(wm + g,     kk + tig));
            a[1] = __float_as_uint(QS(wm + g + 8, kk + tig));
            a[2] = __float_as_uint(QS(wm + g,     kk + tig + 4));
            a[3] = __float_as_uint(QS(wm + g + 8, kk + tig + 4));
#pragma unroll
            for (int nt = 0; nt < 4; nt++) {
                // B[k][n] = K[n][k]: row = key index (n), col = h (k)
                uint32_t b0 = __float_as_uint(KVS(wns + nt * 8 + g, kk + tig));
                uint32_t b1 = __float_as_uint(KVS(wns + nt * 8 + g, kk + tig + 4));
                mma_tf32(sacc[nt], a, b0, b1);
            }
        }

        // Write scaled (+ masked on diagonal tile) S into smP.
        const int rA = wm + g, rB = wm + g + 8;
        const bool diag = (t == qt);
#pragma unroll
        for (int nt = 0; nt < 4; nt++) {
            int cn = wns + nt * 8 + tig * 2;
            float v0 = sacc[nt][0] * inv_scale;
            float v1 = sacc[nt][1] * inv_scale;
            float v2 = sacc[nt][2] * inv_scale;
            float v3 = sacc[nt][3] * inv_scale;
            if (diag) {
                if (cn > rA)     v0 = -1e30f;
                if (cn + 1 > rA) v1 = -1e30f;
                if (cn > rB)     v2 = -1e30f;
                if (cn + 1 > rB) v3 = -1e30f;
            }
            PS(rA, cn) = v0; PS(rA, cn + 1) = v1;
            PS(rB, cn) = v2; PS(rB, cn + 1) = v3;
        }
        __syncthreads();

        // Softmax (round-2 mapping) + write P (tf32) back; also load V tile.
#pragma unroll
        for (int i = 0; i < 4; i++) {
            float s0v = PS(r0 + i, c0s + 0), s1v = PS(r0 + i, c0s + 1);
            float s2v = PS(r0 + i, c0s + 2), s3v = PS(r0 + i, c0s + 3);
            float mx = fmaxf(fmaxf(s0v, s1v), fmaxf(s2v, s3v));
            mx = fmaxf(mx, __shfl_xor_sync(0xffffffffu, mx, 8));
            mx = fmaxf(mx, __shfl_xor_sync(0xffffffffu, mx, 4));
            mx = fmaxf(mx, __shfl_xor_sync(0xffffffffu, mx, 2));
            mx = fmaxf(mx, __shfl_xor_sync(0xffffffffu, mx, 1));
            float mnew = fmaxf(m_run[i], mx);
            float corr = __expf(m_run[i] - mnew);
            m_run[i] = mnew;
            float p0 = __expf(s0v - mnew), p1 = __expf(s1v - mnew);
            float p2 = __expf(s2v - mnew), p3 = __expf(s3v - mnew);
            float ps = p0 + p1 + p2 + p3;
            PS(r0 + i, c0s + 0) = to_tf32(p0);
            PS(r0 + i, c0s + 1) = to_tf32(p1);
            PS(r0 + i, c0s + 2) = to_tf32(p2);
            PS(r0 + i, c0s + 3) = to_tf32(p3);
            ps += __shfl_xor_sync(0xffffffffu, ps, 8);
            ps += __shfl_xor_sync(0xffffffffu, ps, 4);
            ps += __shfl_xor_sync(0xffffffffu, ps, 2);
            ps += __shfl_xor_sync(0xffffffffu, ps, 1);
            l_run[i] = l_run[i] * corr + ps;
            if (tx == 0) smCorr[r0 + i] = corr;
        }
        // V tile load (K no longer needed), tf32.
#pragma unroll
        for (int i = 0; i < 8; i++) {
            int f = i * 256 + tid;
            int row = f >> 5, c = (f & 31) << 2;
            float4 v = *(const float4*)&Vg[(s0 + row) * H_ + c];
            KVS(row, c + 0) = to_tf32(v.x);
            KVS(row, c + 1) = to_tf32(v.y);
            KVS(row, c + 2) = to_tf32(v.z);
            KVS(row, c + 3) = to_tf32(v.w);
        }
        __syncthreads();

        // Rescale O by corr, then O += P @ V (warp 16x64, K=64 in 8 steps).
        float cA = smCorr[wm + g], cB = smCorr[wm + g + 8];
#pragma unroll
        for (int nt = 0; nt < 8; nt++) {
            oacc[nt][0] *= cA; oacc[nt][1] *= cA;
            oacc[nt][2] *= cB; oacc[nt][3] *= cB;
        }
#pragma unroll
        for (int kk = 0; kk < 64; kk += 8) {
            uint32_t a[4];
            a[0] = __float_as_uint(PS(wm + g,     kk + tig));
            a[1] = __float_as_uint(PS(wm + g + 8, kk + tig));
            a[2] = __float_as_uint(PS(wm + g,     kk + tig + 4));
            a[3] = __float_as_uint(PS(wm + g + 8, kk + tig + 4));
#pragma unroll
            for (int nt = 0; nt < 8; nt++) {
                uint32_t b0 = __float_as_uint(KVS(kk + tig,     wno + nt * 8 + g));
                uint32_t b1 = __float_as_uint(KVS(kk + tig + 4, wno + nt * 8 + g));
                mma_tf32(oacc[nt], a, b0, b1);
            }
        }
    }

    // Write unnormalized partials + per-row (m, l).
    const int p = bx;
    if (tx == 0) {
#pragma unroll
        for (int i = 0; i < 4; i++) {
            g_ml[(p * 64 + r0 + i) * 2 + 0] = m_run[i];
            g_ml[(p * 64 + r0 + i) * 2 + 1] = l_run[i];
        }
    }
#pragma unroll
    for (int nt = 0; nt < 8; nt++) {
        int cc = wno + nt * 8 + tig * 2;
        *(float2*)&g_Opart[(p * 64 + wm + g) * H_ + cc] =
            make_float2(oacc[nt][0], oacc[nt][1]);
        *(float2*)&g_Opart[(p * 64 + wm + g + 8) * H_ + cc] =
            make_float2(oacc[nt][2], oacc[nt][3]);
    }
}

// ---------------------------------------------------------------------------
// Kernel 3: merge partials -> final out
// ---------------------------------------------------------------------------
__global__ void attn_merge(float* __restrict__ out) {
    const int qt = blockIdx.x, b = blockIdx.y;
    const int nch = (qt >> 3) + 1;
    const int ubase = (qt < 8)  ? qt
                    : (qt < 16) ? 8 + 2 * (qt - 8)
                    : (qt < 24) ? 24 + 3 * (qt - 16)
                                : 48 + 4 * (qt - 24);
    const int pbase = b * 80 + ubase;
    const int tid = threadIdx.x;
    const int r = tid >> 2;
    const int c0 = (tid & 3) * 32;

    float m = -1e30f;
    for (int c = 0; c < nch; c++)
        m = fmaxf(m, g_ml[((pbase + c) * 64 + r) * 2]);
    float wgt[4];
    float l = 0.f;
    for (int c = 0; c < nch; c++) {
        wgt[c] = __expf(g_ml[((pbase + c) * 64 + r) * 2] - m);
        l += wgt[c] * g_ml[((pbase + c) * 64 + r) * 2 + 1];
    }
    const float invl = 1.f / l;
    const int orow = (b * T_ + qt * 64 + r) * H_;

    for (int cc = 0; cc < 32; cc += 4) {
        float ax = 0.f, ay = 0.f, az = 0.f, aw = 0.f;
        for (int c = 0; c < nch; c++) {
            float4 v = *(const float4*)&g_Opart[((pbase + c) * 64 + r) * H_ + c0 + cc];
            ax += wgt[c] * v.x; ay += wgt[c] * v.y;
            az += wgt[c] * v.z; aw += wgt[c] * v.w;
        }
        *(float4*)&out[orow + c0 + cc] =
            make_float4(ax * invl, ay * invl, az * invl, aw * invl);
    }
}

// ---------------------------------------------------------------------------
// Launch
// ---------------------------------------------------------------------------
extern "C" void kernel_launch(void* const* d_in, const int* in_sizes, int n_in,
                              void* d_out, int out_size) {
    const float* x  = (const float*)d_in[0];
    const float* Wq = (const float*)d_in[1];
    const float* Wk = (const float*)d_in[2];
    const float* Wv = (const float*)d_in[3];
    // d_in[4] = mask: tril by construction -> causal logic used directly.
    float* out = (float*)d_out;

    dim3 gp(BT_ / 128, 3);
    proj_mma<<<gp, 256>>>(x, Wq, Wk, Wv);

    cudaFuncSetAttribute((const void*)attn_part,
                         cudaFuncAttributeMaxDynamicSharedMemorySize, (int)ATTN_SMEM);
    attn_part<<<NUNITS, 256, ATTN_SMEM>>>();

    attn_merge<<<dim3(T_ / 64, B_), 256>>>(out);
}